// round 9
// baseline (speedup 1.0000x reference)
#include <cuda_runtime.h>
#include <math.h>
#include <stdint.h>

#define Bb 32
#define Tt 512
#define Dd 512
#define Hh 2048
#define H3 6144
#define Pp 1024
#define MT (Bb*Tt)   // 16384
#define PFW 8        // weight ring depth (L2, ~250 cyc)
#define PFH 4        // dup-h ring depth (hot, mostly L1)
#define GRID_SCAN 128

typedef unsigned long long ull;

// ---------------- scratch (device globals; padded for prefetch overrun) -----------
__device__ float g_A1[(size_t)MT * 1024];
__device__ float g_A2[(size_t)MT * Hh];
__device__ float g_GI[(size_t)MT * H3];              // gi, layout (T, 3H, B)
__device__ float g_HS[(size_t)Tt * Hh * Bb];         // h history (T, H, B)
__device__ float g_S [(size_t)MT * Pp];
__device__ __align__(256) float g_WT[(size_t)(Hh + PFW) * H3];  // W_hh^T : (K, 3H)
__device__ __align__(256) float g_HD[2][(size_t)(Hh + PFH) * 64]; // dup h ping-pong
__device__ unsigned g_bar_cnt;

// ---------------- helpers ----------------------------------------------------------
__device__ __forceinline__ ull fma2(ull a, ull b, ull c) {
    ull d;
    asm("fma.rn.f32x2 %0, %1, %2, %3;" : "=l"(d) : "l"(a), "l"(b), "l"(c));
    return d;
}
__device__ __forceinline__ ull pack2(float x) {
    ull d;
    asm("mov.b64 %0, {%1, %1};" : "=l"(d) : "f"(x));
    return d;
}
__device__ __forceinline__ float2 ull2f2(ull v) {
    float2 f;
    asm("mov.b64 {%0, %1}, %2;" : "=f"(f.x), "=f"(f.y) : "l"(v));
    return f;
}
// 16B weight load: 2 f32x2 col-pairs (4 cols)
__device__ __forceinline__ void ldg_w2(const float* p, ull& a, ull& b) {
    asm("ld.global.nc.v2.b64 {%0,%1}, [%2];" : "=l"(a), "=l"(b) : "l"(p));
}
// 32B dup-h load: 4 f32x2 (4 batches, each (h,h)), L2 evict-last legal on v4.b64
__device__ __forceinline__ void ldg_h4(const float* p, ull& a, ull& b, ull& c, ull& d) {
    asm("ld.global.nc.L2::evict_last.v4.b64 {%0,%1,%2,%3}, [%4];"
        : "=l"(a), "=l"(b), "=l"(c), "=l"(d) : "l"(p));
}
__device__ __forceinline__ float sigm(float x) { return 1.f / (1.f + expf(-x)); }

// ---------------- generic TN SGEMM (FMA2 core, dup-A smem, double-buffered) --------
// C = act(A @ B^T + bias). aMode: 0 = A row-major (M,K);
//   1 = A stored (T,K,B): A[r][k] = A[(r>>5)*K*32 + k*32 + (r&31)], r = t*32+b
// outMode: 0 = C[r][n];  2 = C stored (T,N,B): addr = t*N*32 + n*32 + b, r = b*T+t
#define BM 128
#define BN 128
#define BK 8
#define TM 8
#define TN 8

__global__ __launch_bounds__(256)
void sgemm_tn(const float* __restrict__ A, const float* __restrict__ B,
              const float* __restrict__ bias, float* __restrict__ C,
              int M, int N, int K, int doRelu, int aMode, int outMode)
{
    __shared__ ull   Asd[2][BK][BM];   // A values pre-duplicated (16 KB)
    __shared__ float Bs [2][BK][BN];   // 8 KB
    const int tid = threadIdx.x;
    const int tx  = tid & 15;
    const int ty  = tid >> 4;
    const int lr  = tid >> 1;
    const int lk  = (tid & 1) * 4;

    const float* Bp = B + (size_t)(blockIdx.x * BN + lr) * K + lk;
    const int rowg = blockIdx.y * BM + lr;
    const float* Ap0 = A + (size_t)rowg * K + lk;
    const float* Ap1 = A + (size_t)(rowg >> 5) * K * 32 + (rowg & 31);

    ull acc2[TM][TN/2];
#pragma unroll
    for (int i = 0; i < TM; i++)
#pragma unroll
        for (int j = 0; j < TN/2; j++) acc2[i][j] = 0ull;

    float rA[4]; float4 rB;
    if (aMode == 0) {
        float4 av = *(const float4*)(Ap0);
        rA[0] = av.x; rA[1] = av.y; rA[2] = av.z; rA[3] = av.w;
    } else {
#pragma unroll
        for (int q = 0; q < 4; q++) rA[q] = Ap1[(size_t)(lk + q) * 32];
    }
    rB = *(const float4*)(Bp);
    int buf = 0;
#pragma unroll
    for (int q = 0; q < 4; q++) Asd[buf][lk + q][lr] = pack2(rA[q]);
    Bs[buf][lk + 0][lr] = rB.x; Bs[buf][lk + 1][lr] = rB.y;
    Bs[buf][lk + 2][lr] = rB.z; Bs[buf][lk + 3][lr] = rB.w;
    __syncthreads();

    for (int k0 = 0; k0 < K; k0 += BK) {
        const bool more = (k0 + BK) < K;
        if (more) {  // global prefetch of next slab into registers
            if (aMode == 0) {
                float4 av = *(const float4*)(Ap0 + k0 + BK);
                rA[0] = av.x; rA[1] = av.y; rA[2] = av.z; rA[3] = av.w;
            } else {
#pragma unroll
                for (int q = 0; q < 4; q++)
                    rA[q] = Ap1[(size_t)(k0 + BK + lk + q) * 32];
            }
            rB = *(const float4*)(Bp + k0 + BK);
        }
#pragma unroll
        for (int k = 0; k < BK; k++) {
            ulonglong2 a01 = *(const ulonglong2*)&Asd[buf][k][ty * TM + 0];
            ulonglong2 a23 = *(const ulonglong2*)&Asd[buf][k][ty * TM + 2];
            ulonglong2 a45 = *(const ulonglong2*)&Asd[buf][k][ty * TM + 4];
            ulonglong2 a67 = *(const ulonglong2*)&Asd[buf][k][ty * TM + 6];
            ulonglong2 bq0 = *(const ulonglong2*)&Bs[buf][k][tx * TN];
            ulonglong2 bq1 = *(const ulonglong2*)&Bs[buf][k][tx * TN + 4];
            ull a[TM] = {a01.x, a01.y, a23.x, a23.y, a45.x, a45.y, a67.x, a67.y};
#pragma unroll
            for (int i = 0; i < TM; i++) {
                acc2[i][0] = fma2(a[i], bq0.x, acc2[i][0]);
                acc2[i][1] = fma2(a[i], bq0.y, acc2[i][1]);
                acc2[i][2] = fma2(a[i], bq1.x, acc2[i][2]);
                acc2[i][3] = fma2(a[i], bq1.y, acc2[i][3]);
            }
        }
        if (more) {
            int nb = buf ^ 1;
#pragma unroll
            for (int q = 0; q < 4; q++) Asd[nb][lk + q][lr] = pack2(rA[q]);
            Bs[nb][lk + 0][lr] = rB.x; Bs[nb][lk + 1][lr] = rB.y;
            Bs[nb][lk + 2][lr] = rB.z; Bs[nb][lk + 3][lr] = rB.w;
            __syncthreads();
            buf = nb;
        }
    }

#pragma unroll
    for (int i = 0; i < TM; i++) {
        int r = blockIdx.y * BM + ty * TM + i;
        int colb = blockIdx.x * BN + tx * TN;
        float v[TN];
#pragma unroll
        for (int j = 0; j < TN/2; j++) {
            float2 f = ull2f2(acc2[i][j]);
            v[2*j] = f.x; v[2*j+1] = f.y;
        }
#pragma unroll
        for (int j = 0; j < TN; j++) {
            v[j] += bias[colb + j];
            if (doRelu) v[j] = fmaxf(v[j], 0.f);
        }
        if (outMode == 0) {
            float* Cp = C + (size_t)r * N + colb;
            *(float4*)(Cp)     = make_float4(v[0], v[1], v[2], v[3]);
            *(float4*)(Cp + 4) = make_float4(v[4], v[5], v[6], v[7]);
        } else {  // r = b*T + t  ->  (t, n, b)
            int t = r & (Tt - 1), b = r >> 9;
            float* Cp = C + (size_t)t * N * 32 + b;
#pragma unroll
            for (int j = 0; j < TN; j++)
                Cp[(size_t)(colb + j) * 32] = v[j];
        }
    }
}

// ---------------- one-time reshapes -------------------------------------------------
__global__ void transpose_whh(const float* __restrict__ Whh, float* __restrict__ WT)
{
    __shared__ float tile[32][33];
    int c0 = blockIdx.x * 32, k0 = blockIdx.y * 32;
    int x = threadIdx.x, y0 = threadIdx.y;
#pragma unroll
    for (int y = y0; y < 32; y += 8)
        tile[y][x] = Whh[(size_t)(c0 + y) * Hh + k0 + x];
    __syncthreads();
#pragma unroll
    for (int y = y0; y < 32; y += 8)
        WT[(size_t)(k0 + y) * H3 + c0 + x] = tile[x][y];
}

__global__ void dup_h0(const float* __restrict__ h0, float* __restrict__ HD0)
{
    int i = blockIdx.x * 256 + threadIdx.x;   // i over H*B
    if (i < Hh * Bb) {
        int c = i >> 5, b = i & 31;
        float v = h0[(size_t)b * Hh + c];
        HD0[(size_t)c * 64 + 2 * b]     = v;
        HD0[(size_t)c * 64 + 2 * b + 1] = v;
    }
}

__global__ void reset_bar() { g_bar_cnt = 0u; }

// ---------------- persistent GRU scan ----------------------------------------------
// 128 blocks x 384 threads. Block = 16 h-cols. 12 warps = gate(3) x ksplit(4).
// Lane: cg = lane&3 (4 groups x 4 cols = 2 colpairs, v2.b64 weight load),
//       bg = lane>>2 (8 groups x 4 batches, v4.b64 dup-h load).
// acc[2 colpairs][4 batches] f32x2. Zero packing in the mainloop.
__global__ __launch_bounds__(384, 1)
void gru_scan(const float* __restrict__ gi0,    // (T, 3H, B)
              const float* __restrict__ WT,     // (K, 3H)
              const float* __restrict__ bhh,
              float* __restrict__ HS,           // (T, H, B)
              float* __restrict__ HD0,          // dup h ping-pong
              float* __restrict__ HD1)
{
    __shared__ float sred[12][16][32];  // [warp][colLocal][batch] 24 KB

    const int tid  = threadIdx.x;
    const int w    = tid >> 5;
    const int lane = tid & 31;
    const int gate = w >> 2;
    const int ks   = w & 3;
    const int cg   = lane & 3;    // 0..3 (4 cols each)
    const int bg   = lane >> 2;   // 0..7 (4 batches each)
    const int colbase = blockIdx.x * 16;
    const int k0 = ks * 512;

    const float* wbase = WT + (size_t)k0 * H3 + (gate * Hh + colbase + 4 * cg);
    const unsigned bar_unit = GRID_SCAN;

    const int ecol = tid >> 4;   // 0..15 (valid for tid<256)
    const int ebp  = tid & 15;   // batches 2ebp, 2ebp+1
    const int colg = colbase + ecol;
    float br = 0.f, bz = 0.f, bn = 0.f;
    if (tid < 256) {
        br = bhh[colg]; bz = bhh[Hh + colg]; bn = bhh[2 * Hh + colg];
    }

    // prime weight ring for t = 0
    ull wbuf[PFW][2];
    {
        const float* p = wbase;
#pragma unroll
        for (int q = 0; q < PFW; q++) { ldg_w2(p, wbuf[q][0], wbuf[q][1]); p += H3; }
    }

    for (int t = 0; t < Tt; t++) {
        const float* hpd = (t & 1) ? HD1 : HD0;   // dup h_{t-1}
        float*       hdn = (t & 1) ? HD0 : HD1;   // dup h_t (epilogue writes)
        const float* gi_t = gi0 + (size_t)t * H3 * Bb;

        ull acc[2][4];
#pragma unroll
        for (int c = 0; c < 2; c++)
#pragma unroll
            for (int b = 0; b < 4; b++) acc[c][b] = 0ull;

        const float* hbase = hpd + (size_t)k0 * 64 + 8 * bg;
        ull hbuf[PFH][4];
        {
            const float* p = hbase;
#pragma unroll
            for (int q = 0; q < PFH; q++) {
                ldg_h4(p, hbuf[q][0], hbuf[q][1], hbuf[q][2], hbuf[q][3]);
                p += 64;
            }
        }
        const float* wpf = wbase + (size_t)PFW * H3;
        const float* hpf = hbase + (size_t)PFH * 64;

        for (int kb = 0; kb < 512; kb += PFW) {
#pragma unroll
            for (int u = 0; u < PFW; u++) {
                const int hu = u & (PFH - 1);
                ull w0 = wbuf[u][0], w1 = wbuf[u][1];
                ull h0v = hbuf[hu][0], h1v = hbuf[hu][1];
                ull h2v = hbuf[hu][2], h3v = hbuf[hu][3];
                ldg_w2(wpf, wbuf[u][0], wbuf[u][1]);
                wpf += H3;                           // padded overrun OK
                ldg_h4(hpf, hbuf[hu][0], hbuf[hu][1], hbuf[hu][2], hbuf[hu][3]);
                hpf += 64;

                acc[0][0] = fma2(w0, h0v, acc[0][0]);
                acc[0][1] = fma2(w0, h1v, acc[0][1]);
                acc[0][2] = fma2(w0, h2v, acc[0][2]);
                acc[0][3] = fma2(w0, h3v, acc[0][3]);
                acc[1][0] = fma2(w1, h0v, acc[1][0]);
                acc[1][1] = fma2(w1, h1v, acc[1][1]);
                acc[1][2] = fma2(w1, h2v, acc[1][2]);
                acc[1][3] = fma2(w1, h3v, acc[1][3]);
            }
        }

        // re-prime weight ring for next step (hides barrier wait)
        {
            const float* p = wbase;
#pragma unroll
            for (int q = 0; q < PFW; q++) { ldg_w2(p, wbuf[q][0], wbuf[q][1]); p += H3; }
        }

        // acc[cp][b]: cols (4cg+2cp, 4cg+2cp+1), batch 4bg+b
#pragma unroll
        for (int cp = 0; cp < 2; cp++) {
#pragma unroll
            for (int b = 0; b < 4; b++) {
                float2 f = ull2f2(acc[cp][b]);
                sred[w][4 * cg + 2 * cp]    [4 * bg + b] = f.x;
                sred[w][4 * cg + 2 * cp + 1][4 * bg + b] = f.y;
            }
        }
        __syncthreads();

        if (tid < 256) {
            float2 gr = {0.f, 0.f}, gz = {0.f, 0.f}, gn = {0.f, 0.f};
#pragma unroll
            for (int s = 0; s < 4; s++) {
                float2 a = *(const float2*)&sred[s]    [ecol][2 * ebp];
                float2 b = *(const float2*)&sred[4 + s][ecol][2 * ebp];
                float2 c = *(const float2*)&sred[8 + s][ecol][2 * ebp];
                gr.x += a.x; gr.y += a.y;
                gz.x += b.x; gz.y += b.y;
                gn.x += c.x; gn.y += c.y;
            }
            float2 ir = *(const float2*)(gi_t + (size_t)colg * 32 + 2 * ebp);
            float2 iz = *(const float2*)(gi_t + (size_t)(Hh + colg) * 32 + 2 * ebp);
            float2 in = *(const float2*)(gi_t + (size_t)(2 * Hh + colg) * 32 + 2 * ebp);
            float4 vv = *(const float4*)(hpd + (size_t)colg * 64 + 4 * ebp);

            float rx = sigm(ir.x + gr.x + br);
            float ry = sigm(ir.y + gr.y + br);
            float zx = sigm(iz.x + gz.x + bz);
            float zy = sigm(iz.y + gz.y + bz);
            float nx = tanhf(in.x + rx * (gn.x + bn));
            float ny = tanhf(in.y + ry * (gn.y + bn));
            float hnx = (1.f - zx) * nx + zx * vv.x;
            float hny = (1.f - zy) * ny + zy * vv.z;
            *(float2*)(HS + (size_t)t * Hh * Bb + (size_t)colg * 32 + 2 * ebp)
                = make_float2(hnx, hny);
            *(float4*)(hdn + (size_t)colg * 64 + 4 * ebp)
                = make_float4(hnx, hnx, hny, hny);
        }

        // -------- grid sync --------
        __syncthreads();
        if (tid == 0) {
            __threadfence();
            atomicAdd(&g_bar_cnt, 1u);
            const unsigned target = (unsigned)(t + 1) * bar_unit;
            unsigned v;
            do {
                asm volatile("ld.global.acquire.gpu.b32 %0, [%1];"
                             : "=r"(v) : "l"(&g_bar_cnt));
                if (v >= target) break;
                __nanosleep(64);
            } while (true);
        }
        __syncthreads();
    }
}

// ---------------- head --------------------------------------------------------------
__global__ __launch_bounds__(256)
void head_kernel(const float* __restrict__ S, const float* __restrict__ Wp,
                 const float* __restrict__ bp, const int* __restrict__ label,
                 float* __restrict__ out)
{
    int w    = blockIdx.x * 8 + (threadIdx.x >> 5);
    int lane = threadIdx.x & 31;
    int bt = w / 3, j = w % 3;
    int t = bt >> 5, b = bt & 31;       // S row = t*32 + b
    int lab = label[b];
    const float* sp = S  + (size_t)bt * Pp;
    const float* wp = Wp + (size_t)(j * 8 + lab) * Pp;
    float sum = 0.f;
    for (int d = lane; d < Pp; d += 32)
        sum = fmaf(sp[d], wp[d], sum);
#pragma unroll
    for (int o = 16; o > 0; o >>= 1) sum += __shfl_xor_sync(0xffffffffu, sum, o);
    if (lane == 0)
        out[(size_t)b * Tt * 3 + t * 3 + j] = sum + bp[j * 8 + lab];
}

__global__ void copy_hlast(const float* __restrict__ srcT, float* __restrict__ dst)
{
    int i = blockIdx.x * 256 + threadIdx.x;      // i = c*32 + b
    if (i < Bb * Hh) {
        int c = i >> 5, b = i & 31;
        dst[(size_t)b * Hh + c] = srcT[i];
    }
}

// ---------------- launch ------------------------------------------------------------
extern "C" void kernel_launch(void* const* d_in, const int* in_sizes, int n_in,
                              void* d_out, int out_size)
{
    (void)in_sizes; (void)n_in; (void)out_size;
    const float* x     = (const float*)d_in[0];
    const int*   label = (const int*)  d_in[1];
    const float* h0    = (const float*)d_in[2];
    const float* W1  = (const float*)d_in[3];  const float* b1  = (const float*)d_in[4];
    const float* W2  = (const float*)d_in[5];  const float* b2  = (const float*)d_in[6];
    const float* Wih = (const float*)d_in[7];  const float* bih = (const float*)d_in[8];
    const float* Whh = (const float*)d_in[9];  const float* bhh = (const float*)d_in[10];
    const float* W3  = (const float*)d_in[11]; const float* b3  = (const float*)d_in[12];
    const float* Wp  = (const float*)d_in[13]; const float* bp  = (const float*)d_in[14];
    float* out = (float*)d_out;

    float *A1, *A2, *GI, *HS, *S, *WT, *HD;
    cudaGetSymbolAddress((void**)&A1, g_A1);
    cudaGetSymbolAddress((void**)&A2, g_A2);
    cudaGetSymbolAddress((void**)&GI, g_GI);
    cudaGetSymbolAddress((void**)&HS, g_HS);
    cudaGetSymbolAddress((void**)&S,  g_S);
    cudaGetSymbolAddress((void**)&WT, g_WT);
    cudaGetSymbolAddress((void**)&HD, g_HD);
    float* HD0 = HD;
    float* HD1 = HD + (size_t)(Hh + PFH) * 64;

    // one-time reshapes + barrier reset
    transpose_whh<<<dim3(H3 / 32, Hh / 32), dim3(32, 8)>>>(Whh, WT);
    dup_h0<<<(Hh * Bb + 255) / 256, 256>>>(h0, HD0);
    reset_bar<<<1, 1>>>();

    // MLP front-end
    sgemm_tn<<<dim3(1024 / BN, MT / BM), 256>>>(x,  W1, b1, A1, MT, 1024, Dd, 1, 0, 0);
    sgemm_tn<<<dim3(Hh   / BN, MT / BM), 256>>>(A1, W2, b2, A2, MT, Hh, 1024, 1, 0, 0);
    // gi written as (T, 3H, B)
    sgemm_tn<<<dim3(H3   / BN, MT / BM), 256>>>(A2, Wih, bih, GI, MT, H3, Hh, 0, 0, 2);

    // persistent GRU scan (all 512 steps in one launch)
    gru_scan<<<GRID_SCAN, 384>>>(GI, WT, bhh, HS, HD0, HD1);

    // out_s = relu(HS @ W3^T + b3); HS is (T,K,B) -> aMode 1, rows r = t*32+b
    sgemm_tn<<<dim3(Pp / BN, MT / BM), 256>>>(HS, W3, b3, S, MT, Pp, Hh, 1, 1, 0);

    head_kernel<<<6144, 256>>>(S, Wp, bp, label, out);
    copy_hlast<<<(Bb * Hh + 255) / 256, 256>>>(HS + (size_t)(Tt - 1) * Hh * Bb,
                                               out + Bb * Tt * 3);
}

// round 10
// speedup vs baseline: 1.1135x; 1.1135x over previous
#include <cuda_runtime.h>
#include <math.h>
#include <stdint.h>

#define Bb 32
#define Tt 512
#define Dd 512
#define Hh 2048
#define H3 6144
#define Pp 1024
#define MT (Bb*Tt)   // 16384
#define PFW 8        // weight ring depth
#define PFH 8        // dup-h ring depth
#define GRID_SCAN 128
#define HDSTEP ((size_t)Hh * 64)   // one dup-h slot: 2048 cols x 32 batches x2

typedef unsigned long long ull;

// ---------------- scratch (device globals) -----------------------------------------
__device__ float g_A1[(size_t)MT * 1024];
__device__ float g_A2[(size_t)MT * Hh];
__device__ float g_GI[(size_t)MT * H3];              // gi, layout (T, 3H, B)
__device__ float g_HS[(size_t)Tt * Hh * Bb];         // h history (T, H, B)
__device__ float g_S [(size_t)MT * Pp];
__device__ __align__(256) float g_WT[(size_t)(Hh + PFW) * H3];   // W_hh^T : (K, 3H)
__device__ __align__(256) float g_HDH[(size_t)(Tt + 1) * HDSTEP + PFH * 64]; // dup-h hist
__device__ unsigned g_bar_cnt;

// ---------------- helpers ----------------------------------------------------------
__device__ __forceinline__ ull fma2(ull a, ull b, ull c) {
    ull d;
    asm("fma.rn.f32x2 %0, %1, %2, %3;" : "=l"(d) : "l"(a), "l"(b), "l"(c));
    return d;
}
__device__ __forceinline__ ull pack2(float x) {
    ull d;
    asm("mov.b64 %0, {%1, %1};" : "=l"(d) : "f"(x));
    return d;
}
__device__ __forceinline__ float2 ull2f2(ull v) {
    float2 f;
    asm("mov.b64 {%0, %1}, %2;" : "=f"(f.x), "=f"(f.y) : "l"(v));
    return f;
}
__device__ __forceinline__ ull mk_evict_last_policy() {
    ull pol;
    asm("createpolicy.fractional.L2::evict_last.b64 %0, 1.0;" : "=l"(pol));
    return pol;
}
// 16B weight load with evict-last cache policy (legal 16B form, R7-proven)
__device__ __forceinline__ void ldg_w2(const float* p, ull pol, ull& a, ull& b) {
    asm("ld.global.nc.L2::cache_hint.v2.b64 {%0,%1}, [%2], %3;"
        : "=l"(a), "=l"(b) : "l"(p), "l"(pol));
}
// 32B dup-h load, plain coherent path (fresh addresses every step)
__device__ __forceinline__ void ldg_h4(const float* p, ull& a, ull& b, ull& c, ull& d) {
    asm("ld.global.v4.b64 {%0,%1,%2,%3}, [%4];"
        : "=l"(a), "=l"(b), "=l"(c), "=l"(d) : "l"(p));
}
__device__ __forceinline__ float sigm(float x) { return 1.f / (1.f + expf(-x)); }

// ---------------- generic TN SGEMM (R7 version: FMA2 + k-pipelined smem) -----------
// C = act(A @ B^T + bias). aMode: 0 = A row-major (M,K);
//   1 = A stored (T,K,B): A[r][k] = A[(r>>5)*K*32 + k*32 + (r&31)], r = t*32+b
// outMode: 0 = C[r][n];  2 = C stored (T,N,B): addr = t*N*32 + n*32 + b, r = b*T+t
#define BM 128
#define BN 128
#define BK 8
#define TM 8
#define TN 8

__global__ __launch_bounds__(256)
void sgemm_tn(const float* __restrict__ A, const float* __restrict__ B,
              const float* __restrict__ bias, float* __restrict__ C,
              int M, int N, int K, int doRelu, int aMode, int outMode)
{
    __shared__ float As[2][BK][BM];
    __shared__ float Bs[2][BK][BN];
    const int tid = threadIdx.x;
    const int tx  = tid & 15;
    const int ty  = tid >> 4;
    const int lr  = tid >> 1;
    const int lk  = (tid & 1) * 4;

    const float* Bp = B + (size_t)(blockIdx.x * BN + lr) * K + lk;
    const int rowg = blockIdx.y * BM + lr;
    const float* Ap0 = A + (size_t)rowg * K + lk;
    const float* Ap1 = A + (size_t)(rowg >> 5) * K * 32 + (rowg & 31);

    ull acc2[TM][TN/2];
#pragma unroll
    for (int i = 0; i < TM; i++)
#pragma unroll
        for (int j = 0; j < TN/2; j++) acc2[i][j] = 0ull;

    float rA[4]; float4 rB;
    if (aMode == 0) {
        float4 av = *(const float4*)(Ap0);
        rA[0] = av.x; rA[1] = av.y; rA[2] = av.z; rA[3] = av.w;
    } else {
#pragma unroll
        for (int q = 0; q < 4; q++) rA[q] = Ap1[(size_t)(lk + q) * 32];
    }
    rB = *(const float4*)(Bp);
    int buf = 0;
#pragma unroll
    for (int q = 0; q < 4; q++) As[buf][lk + q][lr] = rA[q];
    Bs[buf][lk + 0][lr] = rB.x; Bs[buf][lk + 1][lr] = rB.y;
    Bs[buf][lk + 2][lr] = rB.z; Bs[buf][lk + 3][lr] = rB.w;
    __syncthreads();

    for (int k0 = 0; k0 < K; k0 += BK) {
        const bool more = (k0 + BK) < K;
        if (more) {
            if (aMode == 0) {
                float4 av = *(const float4*)(Ap0 + k0 + BK);
                rA[0] = av.x; rA[1] = av.y; rA[2] = av.z; rA[3] = av.w;
            } else {
#pragma unroll
                for (int q = 0; q < 4; q++)
                    rA[q] = Ap1[(size_t)(k0 + BK + lk + q) * 32];
            }
            rB = *(const float4*)(Bp + k0 + BK);
        }
        // smem-fragment software pipeline: load k+1 while computing k
        float4 ca0 = *(const float4*)&As[buf][0][ty * TM];
        float4 ca1 = *(const float4*)&As[buf][0][ty * TM + 4];
        ulonglong2 cb0 = *(const ulonglong2*)&Bs[buf][0][tx * TN];
        ulonglong2 cb1 = *(const ulonglong2*)&Bs[buf][0][tx * TN + 4];
#pragma unroll
        for (int k = 0; k < BK; k++) {
            const int kn = (k + 1) & (BK - 1);
            float4 na0 = *(const float4*)&As[buf][kn][ty * TM];
            float4 na1 = *(const float4*)&As[buf][kn][ty * TM + 4];
            ulonglong2 nb0 = *(const ulonglong2*)&Bs[buf][kn][tx * TN];
            ulonglong2 nb1 = *(const ulonglong2*)&Bs[buf][kn][tx * TN + 4];
            float ar[TM] = {ca0.x, ca0.y, ca0.z, ca0.w, ca1.x, ca1.y, ca1.z, ca1.w};
#pragma unroll
            for (int i = 0; i < TM; i++) {
                ull ap = pack2(ar[i]);
                acc2[i][0] = fma2(ap, cb0.x, acc2[i][0]);
                acc2[i][1] = fma2(ap, cb0.y, acc2[i][1]);
                acc2[i][2] = fma2(ap, cb1.x, acc2[i][2]);
                acc2[i][3] = fma2(ap, cb1.y, acc2[i][3]);
            }
            ca0 = na0; ca1 = na1; cb0 = nb0; cb1 = nb1;
        }
        if (more) {
            int nb = buf ^ 1;
#pragma unroll
            for (int q = 0; q < 4; q++) As[nb][lk + q][lr] = rA[q];
            Bs[nb][lk + 0][lr] = rB.x; Bs[nb][lk + 1][lr] = rB.y;
            Bs[nb][lk + 2][lr] = rB.z; Bs[nb][lk + 3][lr] = rB.w;
            __syncthreads();
            buf = nb;
        }
    }

#pragma unroll
    for (int i = 0; i < TM; i++) {
        int r = blockIdx.y * BM + ty * TM + i;
        int colb = blockIdx.x * BN + tx * TN;
        float v[TN];
#pragma unroll
        for (int j = 0; j < TN/2; j++) {
            float2 f = ull2f2(acc2[i][j]);
            v[2*j] = f.x; v[2*j+1] = f.y;
        }
#pragma unroll
        for (int j = 0; j < TN; j++) {
            v[j] += bias[colb + j];
            if (doRelu) v[j] = fmaxf(v[j], 0.f);
        }
        if (outMode == 0) {
            float* Cp = C + (size_t)r * N + colb;
            *(float4*)(Cp)     = make_float4(v[0], v[1], v[2], v[3]);
            *(float4*)(Cp + 4) = make_float4(v[4], v[5], v[6], v[7]);
        } else {  // r = b*T + t  ->  (t, n, b)
            int t = r & (Tt - 1), b = r >> 9;
            float* Cp = C + (size_t)t * N * 32 + b;
#pragma unroll
            for (int j = 0; j < TN; j++)
                Cp[(size_t)(colb + j) * 32] = v[j];
        }
    }
}

// ---------------- one-time reshapes -------------------------------------------------
__global__ void transpose_whh(const float* __restrict__ Whh, float* __restrict__ WT)
{
    __shared__ float tile[32][33];
    int c0 = blockIdx.x * 32, k0 = blockIdx.y * 32;
    int x = threadIdx.x, y0 = threadIdx.y;
#pragma unroll
    for (int y = y0; y < 32; y += 8)
        tile[y][x] = Whh[(size_t)(c0 + y) * Hh + k0 + x];
    __syncthreads();
#pragma unroll
    for (int y = y0; y < 32; y += 8)
        WT[(size_t)(k0 + y) * H3 + c0 + x] = tile[x][y];
}

__global__ void dup_h0(const float* __restrict__ h0, float* __restrict__ HDH)
{
    int i = blockIdx.x * 256 + threadIdx.x;   // i over H*B
    if (i < Hh * Bb) {
        int c = i >> 5, b = i & 31;
        float v = h0[(size_t)b * Hh + c];
        HDH[(size_t)c * 64 + 2 * b]     = v;
        HDH[(size_t)c * 64 + 2 * b + 1] = v;
    }
}

__global__ void reset_bar() { g_bar_cnt = 0u; }

// ---------------- persistent GRU scan ----------------------------------------------
// 128 blocks x 384 threads. Block = 16 h-cols. 12 warps = gate(3) x ksplit(4).
// Lane: cg = lane&3 (4 groups x 4 cols = 2 colpairs, v2.b64 weight),
//       bg = lane>>2 (8 groups x 4 batches, v4.b64 dup-h).
// acc[2 colpairs][4 batches] f32x2. Zero packing; both rings depth 8.
__global__ __launch_bounds__(384, 1)
void gru_scan(const float* __restrict__ gi0,    // (T, 3H, B)
              const float* __restrict__ WT,     // (K, 3H)
              const float* __restrict__ bhh,
              float* __restrict__ HS,           // (T, H, B)
              float* __restrict__ HDH)          // dup-h history (T+1 slots)
{
    __shared__ float sred[12][16][32];  // [warp][colLocal][batch] 24 KB

    const int tid  = threadIdx.x;
    const int w    = tid >> 5;
    const int lane = tid & 31;
    const int gate = w >> 2;
    const int ks   = w & 3;
    const int cg   = lane & 3;    // 0..3 (4 cols each)
    const int bg   = lane >> 2;   // 0..7 (4 batches each)
    const int colbase = blockIdx.x * 16;
    const int k0 = ks * 512;

    const ull pol = mk_evict_last_policy();
    const float* wbase = WT + (size_t)k0 * H3 + (gate * Hh + colbase + 4 * cg);
    const unsigned bar_unit = GRID_SCAN;

    const int ecol = tid >> 4;   // 0..15 (valid for tid<256)
    const int ebp  = tid & 15;   // batches 2ebp, 2ebp+1
    const int colg = colbase + ecol;
    float br = 0.f, bz = 0.f, bn = 0.f;
    if (tid < 256) {
        br = bhh[colg]; bz = bhh[Hh + colg]; bn = bhh[2 * Hh + colg];
    }

    // prime weight ring for t = 0
    ull wbuf[PFW][2];
    {
        const float* p = wbase;
#pragma unroll
        for (int q = 0; q < PFW; q++) { ldg_w2(p, pol, wbuf[q][0], wbuf[q][1]); p += H3; }
    }

    for (int t = 0; t < Tt; t++) {
        const float* hpd = HDH + (size_t)t * HDSTEP;        // dup h_{t-1} slot
        float*       hdn = HDH + (size_t)(t + 1) * HDSTEP;  // dup h_t slot
        const float* gi_t = gi0 + (size_t)t * H3 * Bb;

        ull acc[2][4];
#pragma unroll
        for (int c = 0; c < 2; c++)
#pragma unroll
            for (int b = 0; b < 4; b++) acc[c][b] = 0ull;

        const float* hbase = hpd + (size_t)k0 * 64 + 8 * bg;
        ull hbuf[PFH][4];
        {
            const float* p = hbase;
#pragma unroll
            for (int q = 0; q < PFH; q++) {
                ldg_h4(p, hbuf[q][0], hbuf[q][1], hbuf[q][2], hbuf[q][3]);
                p += 64;
            }
        }
        const float* wpf = wbase + (size_t)PFW * H3;
        const float* hpf = hbase + (size_t)PFH * 64;

        for (int kb = 0; kb < 512; kb += PFW) {
#pragma unroll
            for (int u = 0; u < PFW; u++) {
                ull w0 = wbuf[u][0], w1 = wbuf[u][1];
                ull h0v = hbuf[u][0], h1v = hbuf[u][1];
                ull h2v = hbuf[u][2], h3v = hbuf[u][3];
                ldg_w2(wpf, pol, wbuf[u][0], wbuf[u][1]);
                wpf += H3;                           // padded overrun OK
                ldg_h4(hpf, hbuf[u][0], hbuf[u][1], hbuf[u][2], hbuf[u][3]);
                hpf += 64;                           // overrun reads next slot (unused)

                acc[0][0] = fma2(w0, h0v, acc[0][0]);
                acc[0][1] = fma2(w0, h1v, acc[0][1]);
                acc[0][2] = fma2(w0, h2v, acc[0][2]);
                acc[0][3] = fma2(w0, h3v, acc[0][3]);
                acc[1][0] = fma2(w1, h0v, acc[1][0]);
                acc[1][1] = fma2(w1, h1v, acc[1][1]);
                acc[1][2] = fma2(w1, h2v, acc[1][2]);
                acc[1][3] = fma2(w1, h3v, acc[1][3]);
            }
        }

        // re-prime weight ring for next step (hides barrier wait)
        {
            const float* p = wbase;
#pragma unroll
            for (int q = 0; q < PFW; q++) { ldg_w2(p, pol, wbuf[q][0], wbuf[q][1]); p += H3; }
        }

        // acc[cp][b]: cols (4cg+2cp, 4cg+2cp+1), batch 4bg+b
#pragma unroll
        for (int cp = 0; cp < 2; cp++) {
#pragma unroll
            for (int b = 0; b < 4; b++) {
                float2 f = ull2f2(acc[cp][b]);
                sred[w][4 * cg + 2 * cp]    [4 * bg + b] = f.x;
                sred[w][4 * cg + 2 * cp + 1][4 * bg + b] = f.y;
            }
        }
        __syncthreads();

        if (tid < 256) {
            float2 gr = {0.f, 0.f}, gz = {0.f, 0.f}, gn = {0.f, 0.f};
#pragma unroll
            for (int s = 0; s < 4; s++) {
                float2 a = *(const float2*)&sred[s]    [ecol][2 * ebp];
                float2 b = *(const float2*)&sred[4 + s][ecol][2 * ebp];
                float2 c = *(const float2*)&sred[8 + s][ecol][2 * ebp];
                gr.x += a.x; gr.y += a.y;
                gz.x += b.x; gz.y += b.y;
                gn.x += c.x; gn.y += c.y;
            }
            float2 ir = *(const float2*)(gi_t + (size_t)colg * 32 + 2 * ebp);
            float2 iz = *(const float2*)(gi_t + (size_t)(Hh + colg) * 32 + 2 * ebp);
            float2 in = *(const float2*)(gi_t + (size_t)(2 * Hh + colg) * 32 + 2 * ebp);
            float4 vv = *(const float4*)(hpd + (size_t)colg * 64 + 4 * ebp);

            float rx = sigm(ir.x + gr.x + br);
            float ry = sigm(ir.y + gr.y + br);
            float zx = sigm(iz.x + gz.x + bz);
            float zy = sigm(iz.y + gz.y + bz);
            float nx = tanhf(in.x + rx * (gn.x + bn));
            float ny = tanhf(in.y + ry * (gn.y + bn));
            float hnx = (1.f - zx) * nx + zx * vv.x;
            float hny = (1.f - zy) * ny + zy * vv.z;
            *(float2*)(HS + (size_t)t * Hh * Bb + (size_t)colg * 32 + 2 * ebp)
                = make_float2(hnx, hny);
            *(float4*)(hdn + (size_t)colg * 64 + 4 * ebp)
                = make_float4(hnx, hnx, hny, hny);
        }

        // -------- grid sync --------
        __syncthreads();
        if (tid == 0) {
            __threadfence();
            atomicAdd(&g_bar_cnt, 1u);
            const unsigned target = (unsigned)(t + 1) * bar_unit;
            unsigned v;
            do {
                asm volatile("ld.global.acquire.gpu.b32 %0, [%1];"
                             : "=r"(v) : "l"(&g_bar_cnt));
                if (v >= target) break;
                __nanosleep(64);
            } while (true);
        }
        __syncthreads();
    }
}

// ---------------- head --------------------------------------------------------------
__global__ __launch_bounds__(256)
void head_kernel(const float* __restrict__ S, const float* __restrict__ Wp,
                 const float* __restrict__ bp, const int* __restrict__ label,
                 float* __restrict__ out)
{
    int w    = blockIdx.x * 8 + (threadIdx.x >> 5);
    int lane = threadIdx.x & 31;
    int bt = w / 3, j = w % 3;
    int t = bt >> 5, b = bt & 31;       // S row = t*32 + b
    int lab = label[b];
    const float* sp = S  + (size_t)bt * Pp;
    const float* wp = Wp + (size_t)(j * 8 + lab) * Pp;
    float sum = 0.f;
    for (int d = lane; d < Pp; d += 32)
        sum = fmaf(sp[d], wp[d], sum);
#pragma unroll
    for (int o = 16; o > 0; o >>= 1) sum += __shfl_xor_sync(0xffffffffu, sum, o);
    if (lane == 0)
        out[(size_t)b * Tt * 3 + t * 3 + j] = sum + bp[j * 8 + lab];
}

__global__ void copy_hlast(const float* __restrict__ srcT, float* __restrict__ dst)
{
    int i = blockIdx.x * 256 + threadIdx.x;      // i = c*32 + b
    if (i < Bb * Hh) {
        int c = i >> 5, b = i & 31;
        dst[(size_t)b * Hh + c] = srcT[i];
    }
}

// ---------------- launch ------------------------------------------------------------
extern "C" void kernel_launch(void* const* d_in, const int* in_sizes, int n_in,
                              void* d_out, int out_size)
{
    (void)in_sizes; (void)n_in; (void)out_size;
    const float* x     = (const float*)d_in[0];
    const int*   label = (const int*)  d_in[1];
    const float* h0    = (const float*)d_in[2];
    const float* W1  = (const float*)d_in[3];  const float* b1  = (const float*)d_in[4];
    const float* W2  = (const float*)d_in[5];  const float* b2  = (const float*)d_in[6];
    const float* Wih = (const float*)d_in[7];  const float* bih = (const float*)d_in[8];
    const float* Whh = (const float*)d_in[9];  const float* bhh = (const float*)d_in[10];
    const float* W3  = (const float*)d_in[11]; const float* b3  = (const float*)d_in[12];
    const float* Wp  = (const float*)d_in[13]; const float* bp  = (const float*)d_in[14];
    float* out = (float*)d_out;

    float *A1, *A2, *GI, *HS, *S, *WT, *HDH;
    cudaGetSymbolAddress((void**)&A1,  g_A1);
    cudaGetSymbolAddress((void**)&A2,  g_A2);
    cudaGetSymbolAddress((void**)&GI,  g_GI);
    cudaGetSymbolAddress((void**)&HS,  g_HS);
    cudaGetSymbolAddress((void**)&S,   g_S);
    cudaGetSymbolAddress((void**)&WT,  g_WT);
    cudaGetSymbolAddress((void**)&HDH, g_HDH);

    // one-time reshapes + barrier reset
    transpose_whh<<<dim3(H3 / 32, Hh / 32), dim3(32, 8)>>>(Whh, WT);
    dup_h0<<<(Hh * Bb + 255) / 256, 256>>>(h0, HDH);
    reset_bar<<<1, 1>>>();

    // MLP front-end
    sgemm_tn<<<dim3(1024 / BN, MT / BM), 256>>>(x,  W1, b1, A1, MT, 1024, Dd, 1, 0, 0);
    sgemm_tn<<<dim3(Hh   / BN, MT / BM), 256>>>(A1, W2, b2, A2, MT, Hh, 1024, 1, 0, 0);
    // gi written as (T, 3H, B)
    sgemm_tn<<<dim3(H3   / BN, MT / BM), 256>>>(A2, Wih, bih, GI, MT, H3, Hh, 0, 0, 2);

    // persistent GRU scan (all 512 steps in one launch)
    gru_scan<<<GRID_SCAN, 384>>>(GI, WT, bhh, HS, HDH);

    // out_s = relu(HS @ W3^T + b3); HS is (T,K,B) -> aMode 1, rows r = t*32+b
    sgemm_tn<<<dim3(Pp / BN, MT / BM), 256>>>(HS, W3, b3, S, MT, Pp, Hh, 1, 1, 0);

    head_kernel<<<6144, 256>>>(S, Wp, bp, label, out);
    copy_hlast<<<(Bb * Hh + 255) / 256, 256>>>(HS + (size_t)(Tt - 1) * Hh * Bb,
                                               out + Bb * Tt * 3);
}

// round 12
// speedup vs baseline: 3.4073x; 3.0600x over previous
#include <cuda_runtime.h>
#include <cuda_bf16.h>
#include <math.h>
#include <stdint.h>

#define Bb 32
#define Tt 512
#define Dd 512
#define Hh 2048
#define H3 6144
#define Pp 1024
#define MT (Bb*Tt)   // 16384
#define PF 8
#define GRID_SCAN 128

typedef unsigned long long ull;

// ---------------- scratch ----------------------------------------------------------
__device__ float g_A1[(size_t)MT * 1024];
__device__ float g_A2[(size_t)MT * Hh];
__device__ float g_GI[(size_t)MT * H3];              // gi ROW-MAJOR (M,3H), r=b*T+t
__device__ float g_HS[(size_t)Tt * Hh * Bb + PF*32]; // h history (T, H, B)
__device__ float g_S [(size_t)MT * Pp];
__device__ __align__(256) float g_WT[(size_t)(Hh + PF) * H3];  // W_hh^T : (K, 3H)
__device__ float g_h0T[(Hh + PF) * Bb];
__device__ unsigned g_bar_cnt;

// ---------------- scalar helpers ---------------------------------------------------
__device__ __forceinline__ ull fma2(ull a, ull b, ull c) {
    ull d; asm("fma.rn.f32x2 %0, %1, %2, %3;" : "=l"(d) : "l"(a), "l"(b), "l"(c));
    return d;
}
__device__ __forceinline__ ull pack2(float x) {
    ull d; asm("mov.b64 %0, {%1, %1};" : "=l"(d) : "f"(x)); return d;
}
__device__ __forceinline__ float2 ull2f2(ull v) {
    float2 f; asm("mov.b64 {%0, %1}, %2;" : "=f"(f.x), "=f"(f.y) : "l"(v)); return f;
}
__device__ __forceinline__ ull mk_evict_last_policy() {
    ull pol; asm("createpolicy.fractional.L2::evict_last.b64 %0, 1.0;" : "=l"(pol));
    return pol;
}
__device__ __forceinline__ float4 ldg_pol(const float* p, ull pol) {
    float4 v;
    asm("ld.global.nc.L2::cache_hint.v4.f32 {%0,%1,%2,%3}, [%4], %5;"
        : "=f"(v.x), "=f"(v.y), "=f"(v.z), "=f"(v.w) : "l"(p), "l"(pol));
    return v;
}
__device__ __forceinline__ float sigm(float x) { return 1.f / (1.f + expf(-x)); }
__device__ __forceinline__ uint32_t smem_u32(const void* p) {
    uint32_t a;
    asm("{ .reg .u64 t; cvta.to.shared.u64 t, %1; cvt.u32.u64 %0, t; }" : "=r"(a) : "l"(p));
    return a;
}

// ---------------- mma.sync primitives ----------------------------------------------
__device__ __forceinline__ void ldsm_x4(uint32_t* r, uint32_t addr) {
    asm volatile("ldmatrix.sync.aligned.m8n8.x4.shared.b16 {%0,%1,%2,%3}, [%4];"
                 : "=r"(r[0]), "=r"(r[1]), "=r"(r[2]), "=r"(r[3]) : "r"(addr));
}
__device__ __forceinline__ void ldsm_x2(uint32_t* r, uint32_t addr) {
    asm volatile("ldmatrix.sync.aligned.m8n8.x2.shared.b16 {%0,%1}, [%2];"
                 : "=r"(r[0]), "=r"(r[1]) : "r"(addr));
}
__device__ __forceinline__ void mma_bf16(float* c, const uint32_t* a, const uint32_t* b) {
    asm volatile("mma.sync.aligned.m16n8k16.row.col.f32.bf16.bf16.f32 "
                 "{%0,%1,%2,%3}, {%4,%5,%6,%7}, {%8,%9}, {%0,%1,%2,%3};"
                 : "+f"(c[0]), "+f"(c[1]), "+f"(c[2]), "+f"(c[3])
                 : "r"(a[0]), "r"(a[1]), "r"(a[2]), "r"(a[3]), "r"(b[0]), "r"(b[1]));
}
// pack two floats into (hi, lo) bf16x2 words
__device__ __forceinline__ void cvt_hilo(float x, float y, uint32_t& hi, uint32_t& lo) {
    __nv_bfloat16 hx = __float2bfloat16(x), hy = __float2bfloat16(y);
    float lx = x - __bfloat162float(hx), ly = y - __bfloat162float(hy);
    __nv_bfloat162 ph = __halves2bfloat162(hx, hy);
    __nv_bfloat162 pl = __halves2bfloat162(__float2bfloat16(lx), __float2bfloat16(ly));
    hi = *reinterpret_cast<uint32_t*>(&ph);
    lo = *reinterpret_cast<uint32_t*>(&pl);
}

// ---------------- split-bf16 mma.sync GEMM -----------------------------------------
// C = act(A[M,K] @ B[N,K]^T + bias), all row-major, M,N multiples of 128, K of 16.
// Block 256 threads = 8 warps (2 M x 4 N), warp tile 64x32, BK=16, double-buffered.
#define MMROW 48   // smem row stride bytes (16 k-bf16 = 32B + 16B pad, conflict-free)
#define MMSTG 24576  // one stage: AH/AL/BH/BL each 128*48
__global__ __launch_bounds__(256)
void mma_gemm(const float* __restrict__ A, const float* __restrict__ B,
              const float* __restrict__ bias, float* __restrict__ C,
              int M, int N, int K, int doRelu)
{
    extern __shared__ char sm[];
    const uint32_t sbase = smem_u32(sm);
    const int tid  = threadIdx.x;
    const int wid  = tid >> 5;
    const int lane = tid & 31;
    const int wm   = wid & 1;      // 0..1
    const int wn   = wid >> 1;     // 0..3
    const int mb   = blockIdx.y, nb = blockIdx.x;

    // staging coords: rows tid>>2 and +64, float4 at col (tid&3)*4
    const int srow = tid >> 2;
    const int scol = (tid & 3) * 4;
    const float* Ag = A + (size_t)(mb * 128 + srow) * K + scol;
    const float* Bg = B + (size_t)(nb * 128 + srow) * K + scol;
    const size_t g64 = (size_t)64 * K;

    float c[4][4][4];
#pragma unroll
    for (int i = 0; i < 4; i++)
#pragma unroll
        for (int j = 0; j < 4; j++)
#pragma unroll
            for (int q = 0; q < 4; q++) c[i][j][q] = 0.f;

    const int nk = K >> 4;
    float4 ra0, ra1, rb0, rb1;
    ra0 = *(const float4*)(Ag); ra1 = *(const float4*)(Ag + g64);
    rb0 = *(const float4*)(Bg); rb1 = *(const float4*)(Bg + g64);

    int buf = 0;
    // store stage helper (as lambda-ish macro)
#define STORE_STAGE(BUF)                                                          \
    {                                                                             \
        uint32_t off = (BUF) * MMSTG;                                             \
        uint32_t h, l;                                                            \
        uint32_t a0 = off + srow * MMROW + scol * 2;                              \
        cvt_hilo(ra0.x, ra0.y, h, l);                                             \
        *(uint32_t*)(sm + a0)        = h; *(uint32_t*)(sm + a0 + 6144)     = l;   \
        cvt_hilo(ra0.z, ra0.w, h, l);                                             \
        *(uint32_t*)(sm + a0 + 4)    = h; *(uint32_t*)(sm + a0 + 6148)     = l;   \
        uint32_t a1 = a0 + 64 * MMROW;                                            \
        cvt_hilo(ra1.x, ra1.y, h, l);                                             \
        *(uint32_t*)(sm + a1)        = h; *(uint32_t*)(sm + a1 + 6144)     = l;   \
        cvt_hilo(ra1.z, ra1.w, h, l);                                             \
        *(uint32_t*)(sm + a1 + 4)    = h; *(uint32_t*)(sm + a1 + 6148)     = l;   \
        uint32_t b0 = off + 12288 + srow * MMROW + scol * 2;                      \
        cvt_hilo(rb0.x, rb0.y, h, l);                                             \
        *(uint32_t*)(sm + b0)        = h; *(uint32_t*)(sm + b0 + 6144)     = l;   \
        cvt_hilo(rb0.z, rb0.w, h, l);                                             \
        *(uint32_t*)(sm + b0 + 4)    = h; *(uint32_t*)(sm + b0 + 6148)     = l;   \
        uint32_t b1 = b0 + 64 * MMROW;                                            \
        cvt_hilo(rb1.x, rb1.y, h, l);                                             \
        *(uint32_t*)(sm + b1)        = h; *(uint32_t*)(sm + b1 + 6144)     = l;   \
        cvt_hilo(rb1.z, rb1.w, h, l);                                             \
        *(uint32_t*)(sm + b1 + 4)    = h; *(uint32_t*)(sm + b1 + 6148)     = l;   \
    }

    STORE_STAGE(0);
    __syncthreads();

    // ldmatrix lane addressing (within-warp)
    const uint32_t a_lrow = (uint32_t)(wm * 64 + (lane & 15)) * MMROW + ((lane >> 4) * 16);
    const uint32_t b_lrow = (uint32_t)(wn * 32 + (lane & 7)) * MMROW + (((lane >> 3) & 1) * 16);

    for (int kt = 0; kt < nk; kt++) {
        if (kt + 1 < nk) {
            const float* Agn = Ag + (kt + 1) * 16;
            const float* Bgn = Bg + (kt + 1) * 16;
            ra0 = *(const float4*)(Agn); ra1 = *(const float4*)(Agn + g64);
            rb0 = *(const float4*)(Bgn); rb1 = *(const float4*)(Bgn + g64);
        }
        const uint32_t off = buf * MMSTG;
        uint32_t ahi[4][4], alo[4][4];
#pragma unroll
        for (int mf = 0; mf < 4; mf++) {
            uint32_t ad = sbase + off + a_lrow + (uint32_t)mf * 16 * MMROW;
            ldsm_x4(ahi[mf], ad);
            ldsm_x4(alo[mf], ad + 6144);
        }
#pragma unroll
        for (int nf = 0; nf < 4; nf++) {
            uint32_t bd = sbase + off + 12288 + b_lrow + (uint32_t)nf * 8 * MMROW;
            uint32_t bhi[2], blo[2];
            ldsm_x2(bhi, bd);
            ldsm_x2(blo, bd + 6144);
#pragma unroll
            for (int mf = 0; mf < 4; mf++) {
                mma_bf16(c[mf][nf], ahi[mf], bhi);
                mma_bf16(c[mf][nf], ahi[mf], blo);
                mma_bf16(c[mf][nf], alo[mf], bhi);
            }
        }
        if (kt + 1 < nk) {
            STORE_STAGE(buf ^ 1);
            __syncthreads();
            buf ^= 1;
        }
    }
#undef STORE_STAGE

    // epilogue: c[mf][nf] rows r0=.. lane/4, r1=+8; cols 2*(lane&3)
    const int rbase = mb * 128 + wm * 64 + (lane >> 2);
    const int cbase = nb * 128 + wn * 32 + 2 * (lane & 3);
#pragma unroll
    for (int mf = 0; mf < 4; mf++) {
#pragma unroll
        for (int nf = 0; nf < 4; nf++) {
            int col = cbase + nf * 8;
            float b0 = bias[col], b1 = bias[col + 1];
            float v0 = c[mf][nf][0] + b0, v1 = c[mf][nf][1] + b1;
            float v2 = c[mf][nf][2] + b0, v3 = c[mf][nf][3] + b1;
            if (doRelu) {
                v0 = fmaxf(v0, 0.f); v1 = fmaxf(v1, 0.f);
                v2 = fmaxf(v2, 0.f); v3 = fmaxf(v3, 0.f);
            }
            int r0 = rbase + mf * 16;
            *(float2*)(C + (size_t)r0 * N + col)       = make_float2(v0, v1);
            *(float2*)(C + (size_t)(r0 + 8) * N + col) = make_float2(v2, v3);
        }
    }
}

// ---------------- scalar SGEMM (R7) ------------------------------------------------
#define BM 128
#define BN 128
#define BK 8
#define TM 8
#define TN 8

__global__ __launch_bounds__(256)
void sgemm_tn(const float* __restrict__ A, const float* __restrict__ B,
              const float* __restrict__ bias, float* __restrict__ C,
              int M, int N, int K, int doRelu, int aMode)
{
    __shared__ float As[2][BK][BM];
    __shared__ float Bs[2][BK][BN];
    const int tid = threadIdx.x;
    const int tx  = tid & 15;
    const int ty  = tid >> 4;
    const int lr  = tid >> 1;
    const int lk  = (tid & 1) * 4;

    const float* Bp = B + (size_t)(blockIdx.x * BN + lr) * K + lk;
    const int rowg = blockIdx.y * BM + lr;
    const float* Ap0 = A + (size_t)rowg * K + lk;
    const float* Ap1 = A + (size_t)(rowg >> 5) * K * 32 + (rowg & 31);

    ull acc2[TM][TN/2];
#pragma unroll
    for (int i = 0; i < TM; i++)
#pragma unroll
        for (int j = 0; j < TN/2; j++) acc2[i][j] = 0ull;

    float rA[4]; float4 rB;
    if (aMode == 0) {
        float4 av = *(const float4*)(Ap0);
        rA[0] = av.x; rA[1] = av.y; rA[2] = av.z; rA[3] = av.w;
    } else {
#pragma unroll
        for (int q = 0; q < 4; q++) rA[q] = Ap1[(size_t)(lk + q) * 32];
    }
    rB = *(const float4*)(Bp);
    int buf = 0;
#pragma unroll
    for (int q = 0; q < 4; q++) As[buf][lk + q][lr] = rA[q];
    Bs[buf][lk+0][lr]=rB.x; Bs[buf][lk+1][lr]=rB.y; Bs[buf][lk+2][lr]=rB.z; Bs[buf][lk+3][lr]=rB.w;
    __syncthreads();

    for (int k0 = 0; k0 < K; k0 += BK) {
        const bool more = (k0 + BK) < K;
        if (more) {
            if (aMode == 0) {
                float4 av = *(const float4*)(Ap0 + k0 + BK);
                rA[0] = av.x; rA[1] = av.y; rA[2] = av.z; rA[3] = av.w;
            } else {
#pragma unroll
                for (int q = 0; q < 4; q++)
                    rA[q] = Ap1[(size_t)(k0 + BK + lk + q) * 32];
            }
            rB = *(const float4*)(Bp + k0 + BK);
        }
        float4 ca0 = *(const float4*)&As[buf][0][ty * TM];
        float4 ca1 = *(const float4*)&As[buf][0][ty * TM + 4];
        ulonglong2 cb0 = *(const ulonglong2*)&Bs[buf][0][tx * TN];
        ulonglong2 cb1 = *(const ulonglong2*)&Bs[buf][0][tx * TN + 4];
#pragma unroll
        for (int k = 0; k < BK; k++) {
            const int kn = (k + 1) & (BK - 1);
            float4 na0 = *(const float4*)&As[buf][kn][ty * TM];
            float4 na1 = *(const float4*)&As[buf][kn][ty * TM + 4];
            ulonglong2 nb0 = *(const ulonglong2*)&Bs[buf][kn][tx * TN];
            ulonglong2 nb1 = *(const ulonglong2*)&Bs[buf][kn][tx * TN + 4];
            float ar[TM] = {ca0.x, ca0.y, ca0.z, ca0.w, ca1.x, ca1.y, ca1.z, ca1.w};
#pragma unroll
            for (int i = 0; i < TM; i++) {
                ull ap = pack2(ar[i]);
                acc2[i][0] = fma2(ap, cb0.x, acc2[i][0]);
                acc2[i][1] = fma2(ap, cb0.y, acc2[i][1]);
                acc2[i][2] = fma2(ap, cb1.x, acc2[i][2]);
                acc2[i][3] = fma2(ap, cb1.y, acc2[i][3]);
            }
            ca0 = na0; ca1 = na1; cb0 = nb0; cb1 = nb1;
        }
        if (more) {
            int nb2 = buf ^ 1;
#pragma unroll
            for (int q = 0; q < 4; q++) As[nb2][lk + q][lr] = rA[q];
            Bs[nb2][lk+0][lr]=rB.x; Bs[nb2][lk+1][lr]=rB.y; Bs[nb2][lk+2][lr]=rB.z; Bs[nb2][lk+3][lr]=rB.w;
            __syncthreads();
            buf = nb2;
        }
    }

#pragma unroll
    for (int i = 0; i < TM; i++) {
        int r = blockIdx.y * BM + ty * TM + i;
        int colb = blockIdx.x * BN + tx * TN;
        float v[TN];
#pragma unroll
        for (int j = 0; j < TN/2; j++) { float2 f = ull2f2(acc2[i][j]); v[2*j]=f.x; v[2*j+1]=f.y; }
#pragma unroll
        for (int j = 0; j < TN; j++) {
            v[j] += bias[colb + j];
            if (doRelu) v[j] = fmaxf(v[j], 0.f);
        }
        float* Cp = C + (size_t)r * N + colb;
        *(float4*)(Cp)     = make_float4(v[0], v[1], v[2], v[3]);
        *(float4*)(Cp + 4) = make_float4(v[4], v[5], v[6], v[7]);
    }
}

// ---------------- one-time reshapes -------------------------------------------------
__global__ void transpose_whh(const float* __restrict__ Whh, float* __restrict__ WT)
{
    __shared__ float tile[32][33];
    int c0 = blockIdx.x * 32, k0 = blockIdx.y * 32;
    int x = threadIdx.x, y0 = threadIdx.y;
#pragma unroll
    for (int y = y0; y < 32; y += 8)
        tile[y][x] = Whh[(size_t)(c0 + y) * Hh + k0 + x];
    __syncthreads();
#pragma unroll
    for (int y = y0; y < 32; y += 8)
        WT[(size_t)(k0 + y) * H3 + c0 + x] = tile[x][y];
}

__global__ void transpose_h0(const float* __restrict__ h0, float* __restrict__ h0T)
{
    int i = blockIdx.x * 256 + threadIdx.x;
    if (i < Hh * Bb) { int c = i >> 5, b = i & 31; h0T[i] = h0[(size_t)b * Hh + c]; }
}

__global__ void reset_bar() { g_bar_cnt = 0u; }

// ---------------- persistent GRU scan (R7 core; gi row-major epilogue) -------------
__global__ __launch_bounds__(384, 1)
void gru_scan(const float* __restrict__ gi0,    // row-major (M,3H), r=b*T+t
              const float* __restrict__ h0T,    // (H, B)
              const float* __restrict__ WT,     // (K, 3H)
              const float* __restrict__ bhh,
              float* __restrict__ HS)           // (T, H, B)
{
    __shared__ float2 sred[12][16][16];

    const int tid  = threadIdx.x;
    const int w    = tid >> 5;
    const int lane = tid & 31;
    const int gate = w >> 2;
    const int ks   = w & 3;
    const int cg   = lane >> 3;
    const int bg   = lane & 7;
    const int colbase = blockIdx.x * 16;
    const int k0 = ks * 512;

    const ull pol = mk_evict_last_policy();
    const float* wbase = WT + (size_t)k0 * H3 + (gate * Hh + colbase + 4 * cg);
    const unsigned bar_unit = GRID_SCAN;

    const int ecol = tid >> 4;
    const int ebp  = tid & 15;
    const int colg = colbase + ecol;
    float br = 0.f, bz = 0.f, bn = 0.f;
    if (tid < 256) { br = bhh[colg]; bz = bhh[Hh + colg]; bn = bhh[2 * Hh + colg]; }

    float4 wbuf[PF];
    {
        const float* p = wbase;
#pragma unroll
        for (int q = 0; q < PF; q++) { wbuf[q] = ldg_pol(p, pol); p += H3; }
    }

    for (int t = 0; t < Tt; t++) {
        const float* hp = (t == 0) ? h0T : (HS + (size_t)(t - 1) * Hh * Bb);

        ull acc[4][2];
#pragma unroll
        for (int c = 0; c < 4; c++) { acc[c][0] = 0ull; acc[c][1] = 0ull; }

        const float* hbase = hp + (size_t)k0 * 32 + 4 * bg;
        ulonglong2 hbuf[PF];
        {
            const float* p = hbase;
#pragma unroll
            for (int q = 0; q < PF; q++) { hbuf[q] = *(const ulonglong2*)p; p += 32; }
        }
        const float* wpf = wbase + (size_t)PF * H3;
        const float* hpf = hbase + (size_t)PF * 32;

        for (int kb = 0; kb < 512; kb += PF) {
#pragma unroll
            for (int u = 0; u < PF; u++) {
                float4     w4 = wbuf[u];
                ulonglong2 hq = hbuf[u];
                wbuf[u] = ldg_pol(wpf, pol);         wpf += H3;
                hbuf[u] = *(const ulonglong2*)hpf;   hpf += 32;

                ull p0 = pack2(w4.x), p1 = pack2(w4.y);
                ull p2 = pack2(w4.z), p3 = pack2(w4.w);
                acc[0][0] = fma2(p0, hq.x, acc[0][0]);
                acc[0][1] = fma2(p0, hq.y, acc[0][1]);
                acc[1][0] = fma2(p1, hq.x, acc[1][0]);
                acc[1][1] = fma2(p1, hq.y, acc[1][1]);
                acc[2][0] = fma2(p2, hq.x, acc[2][0]);
                acc[2][1] = fma2(p2, hq.y, acc[2][1]);
                acc[3][0] = fma2(p3, hq.x, acc[3][0]);
                acc[3][1] = fma2(p3, hq.y, acc[3][1]);
            }
        }

        {   // re-prime weight ring for next step
            const float* p = wbase;
#pragma unroll
            for (int q = 0; q < PF; q++) { wbuf[q] = ldg_pol(p, pol); p += H3; }
        }

#pragma unroll
        for (int c = 0; c < 4; c++) {
            sred[w][4 * cg + c][2 * bg + 0] = ull2f2(acc[c][0]);
            sred[w][4 * cg + c][2 * bg + 1] = ull2f2(acc[c][1]);
        }
        __syncthreads();

        if (tid < 256) {
            float2 gr = {0.f, 0.f}, gz = {0.f, 0.f}, gn = {0.f, 0.f};
#pragma unroll
            for (int s = 0; s < 4; s++) {
                float2 a = sred[s][ecol][ebp];      gr.x += a.x; gr.y += a.y;
                float2 b = sred[4 + s][ecol][ebp];  gz.x += b.x; gz.y += b.y;
                float2 c = sred[8 + s][ecol][ebp];  gn.x += c.x; gn.y += c.y;
            }
            // gi row-major: rows r = b*T + t, batches 2ebp, 2ebp+1
            const float* g0 = gi0 + ((size_t)(2 * ebp) * Tt + t) * H3 + colg;
            const float* g1 = g0 + (size_t)Tt * H3;
            float2 ir = make_float2(g0[0],      g1[0]);
            float2 iz = make_float2(g0[Hh],     g1[Hh]);
            float2 in = make_float2(g0[2 * Hh], g1[2 * Hh]);
            float2 hv = *(const float2*)(hp + (size_t)colg * 32 + 2 * ebp);

            float rx = sigm(ir.x + gr.x + br);
            float ry = sigm(ir.y + gr.y + br);
            float zx = sigm(iz.x + gz.x + bz);
            float zy = sigm(iz.y + gz.y + bz);
            float nx = tanhf(in.x + rx * (gn.x + bn));
            float ny = tanhf(in.y + ry * (gn.y + bn));
            float2 hn;
            hn.x = (1.f - zx) * nx + zx * hv.x;
            hn.y = (1.f - zy) * ny + zy * hv.y;
            *(float2*)(HS + (size_t)t * Hh * Bb + (size_t)colg * 32 + 2 * ebp) = hn;
        }

        __syncthreads();
        if (tid == 0) {
            __threadfence();
            atomicAdd(&g_bar_cnt, 1u);
            const unsigned target = (unsigned)(t + 1) * bar_unit;
            unsigned v;
            do {
                asm volatile("ld.global.acquire.gpu.b32 %0, [%1];" : "=r"(v) : "l"(&g_bar_cnt));
                if (v >= target) break;
                __nanosleep(64);
            } while (true);
        }
        __syncthreads();
    }
}

// ---------------- head --------------------------------------------------------------
__global__ __launch_bounds__(256)
void head_kernel(const float* __restrict__ S, const float* __restrict__ Wp,
                 const float* __restrict__ bp, const int* __restrict__ label,
                 float* __restrict__ out)
{
    int w    = blockIdx.x * 8 + (threadIdx.x >> 5);
    int lane = threadIdx.x & 31;
    int bt = w / 3, j = w % 3;
    int t = bt >> 5, b = bt & 31;
    int lab = label[b];
    const float* sp = S  + (size_t)bt * Pp;
    const float* wp = Wp + (size_t)(j * 8 + lab) * Pp;
    float sum = 0.f;
    for (int d = lane; d < Pp; d += 32)
        sum = fmaf(sp[d], wp[d], sum);
#pragma unroll
    for (int o = 16; o > 0; o >>= 1) sum += __shfl_xor_sync(0xffffffffu, sum, o);
    if (lane == 0)
        out[(size_t)b * Tt * 3 + t * 3 + j] = sum + bp[j * 8 + lab];
}

__global__ void copy_hlast(const float* __restrict__ srcT, float* __restrict__ dst)
{
    int i = blockIdx.x * 256 + threadIdx.x;
    if (i < Bb * Hh) { int c = i >> 5, b = i & 31; dst[(size_t)b * Hh + c] = srcT[i]; }
}

// ---------------- launch ------------------------------------------------------------
extern "C" void kernel_launch(void* const* d_in, const int* in_sizes, int n_in,
                              void* d_out, int out_size)
{
    (void)in_sizes; (void)n_in; (void)out_size;
    const float* x     = (const float*)d_in[0];
    const int*   label = (const int*)  d_in[1];
    const float* h0    = (const float*)d_in[2];
    const float* W1  = (const float*)d_in[3];  const float* b1  = (const float*)d_in[4];
    const float* W2  = (const float*)d_in[5];  const float* b2  = (const float*)d_in[6];
    const float* Wih = (const float*)d_in[7];  const float* bih = (const float*)d_in[8];
    const float* Whh = (const float*)d_in[9];  const float* bhh = (const float*)d_in[10];
    const float* W3  = (const float*)d_in[11]; const float* b3  = (const float*)d_in[12];
    const float* Wp  = (const float*)d_in[13]; const float* bp  = (const float*)d_in[14];
    float* out = (float*)d_out;

    float *A1, *A2, *GI, *HS, *S, *WT, *h0T;
    cudaGetSymbolAddress((void**)&A1,  g_A1);
    cudaGetSymbolAddress((void**)&A2,  g_A2);
    cudaGetSymbolAddress((void**)&GI,  g_GI);
    cudaGetSymbolAddress((void**)&HS,  g_HS);
    cudaGetSymbolAddress((void**)&S,   g_S);
    cudaGetSymbolAddress((void**)&WT,  g_WT);
    cudaGetSymbolAddress((void**)&h0T, g_h0T);

    transpose_whh<<<dim3(H3 / 32, Hh / 32), dim3(32, 8)>>>(Whh, WT);
    transpose_h0<<<(Hh * Bb + 255) / 256, 256>>>(h0, h0T);
    reset_bar<<<1, 1>>>();

    // W1: scalar (K=512)
    sgemm_tn<<<dim3(1024 / BN, MT / BM), 256>>>(x, W1, b1, A1, MT, 1024, Dd, 1, 0);
    // W2, Wih: tensor cores (split-bf16 mma.sync), outputs row-major
    mma_gemm<<<dim3(Hh / 128, MT / 128), 256, 2 * MMSTG>>>(A1, W2, b2, A2,
                                                           MT, Hh, 1024, 1);
    mma_gemm<<<dim3(H3 / 128, MT / 128), 256, 2 * MMSTG>>>(A2, Wih, bih, GI,
                                                           MT, H3, Hh, 0);
    // persistent GRU scan (gi row-major)
    gru_scan<<<GRID_SCAN, 384>>>(GI, h0T, WT, bhh, HS);
    // W3: scalar, A = HS (T,K,B) -> aMode 1
    sgemm_tn<<<dim3(Pp / BN, MT / BM), 256>>>(HS, W3, b3, S, MT, Pp, Hh, 1, 1);

    head_kernel<<<6144, 256>>>(S, Wp, bp, label, out);
    copy_hlast<<<(Bb * Hh + 255) / 256, 256>>>(HS + (size_t)(Tt - 1) * Hh * Bb,
                                               out + Bb * Tt * 3);
}

// round 13
// speedup vs baseline: 5.7638x; 1.6916x over previous
#include <cuda_runtime.h>
#include <cuda_bf16.h>
#include <math.h>
#include <stdint.h>

#define Bb 32
#define Tt 512
#define Dd 512
#define Hh 2048
#define H3 6144
#define Pp 1024
#define MT (Bb*Tt)   // 16384
#define GRID_SCAN 128

typedef unsigned long long ull;

// ---------------- scratch ----------------------------------------------------------
__device__ float g_A1[(size_t)MT * 1024];
__device__ float g_A2[(size_t)MT * Hh];
__device__ float g_GI[(size_t)MT * H3];               // gi row-major (M,3H), r=b*T+t
__device__ float g_HS[(size_t)MT * Hh];               // h history ROW-MAJOR r=t*32+b
__device__ float g_S [(size_t)MT * Pp];
// W_hh fragment-packed: [blk(128)][nf(6)][chunk(128)][lane(32)][4 regs] + 4-chunk pad
__device__ __align__(256) uint32_t g_WF[(size_t)128 * 6 * 128 * 128 + 512];
// h fragment ping-pong: [chunk(128)][frag(2)][hi 128 u32 | lo 128 u32] + 4-chunk pad
__device__ __align__(256) uint32_t g_HF[2][128 * 512 + 4 * 512];
__device__ unsigned g_bar_cnt;

// ---------------- helpers ----------------------------------------------------------
__device__ __forceinline__ float sigm(float x) { return 1.f / (1.f + expf(-x)); }
__device__ __forceinline__ uint32_t smem_u32(const void* p) {
    uint32_t a;
    asm("{ .reg .u64 t; cvta.to.shared.u64 t, %1; cvt.u32.u64 %0, t; }" : "=r"(a) : "l"(p));
    return a;
}
__device__ __forceinline__ void ldsm_x4(uint32_t* r, uint32_t addr) {
    asm volatile("ldmatrix.sync.aligned.m8n8.x4.shared.b16 {%0,%1,%2,%3}, [%4];"
                 : "=r"(r[0]), "=r"(r[1]), "=r"(r[2]), "=r"(r[3]) : "r"(addr));
}
__device__ __forceinline__ void ldsm_x2(uint32_t* r, uint32_t addr) {
    asm volatile("ldmatrix.sync.aligned.m8n8.x2.shared.b16 {%0,%1}, [%2];"
                 : "=r"(r[0]), "=r"(r[1]) : "r"(addr));
}
__device__ __forceinline__ void mma_bf16(float* c, const uint32_t* a, const uint32_t* b) {
    asm volatile("mma.sync.aligned.m16n8k16.row.col.f32.bf16.bf16.f32 "
                 "{%0,%1,%2,%3}, {%4,%5,%6,%7}, {%8,%9}, {%0,%1,%2,%3};"
                 : "+f"(c[0]), "+f"(c[1]), "+f"(c[2]), "+f"(c[3])
                 : "r"(a[0]), "r"(a[1]), "r"(a[2]), "r"(a[3]), "r"(b[0]), "r"(b[1]));
}
__device__ __forceinline__ void cvt_hilo(float x, float y, uint32_t& hi, uint32_t& lo) {
    __nv_bfloat16 hx = __float2bfloat16(x), hy = __float2bfloat16(y);
    float lx = x - __bfloat162float(hx), ly = y - __bfloat162float(hy);
    __nv_bfloat162 ph = __halves2bfloat162(hx, hy);
    __nv_bfloat162 pl = __halves2bfloat162(__float2bfloat16(lx), __float2bfloat16(ly));
    hi = *reinterpret_cast<uint32_t*>(&ph);
    lo = *reinterpret_cast<uint32_t*>(&pl);
}

// ---------------- split-bf16 mma.sync GEMM (proven R12) ----------------------------
#define MMROW 48
#define MMSTG 24576
__global__ __launch_bounds__(256)
void mma_gemm(const float* __restrict__ A, const float* __restrict__ B,
              const float* __restrict__ bias, float* __restrict__ C,
              int M, int N, int K, int doRelu)
{
    extern __shared__ char sm[];
    const uint32_t sbase = smem_u32(sm);
    const int tid  = threadIdx.x;
    const int wid  = tid >> 5;
    const int lane = tid & 31;
    const int wm   = wid & 1;
    const int wn   = wid >> 1;
    const int mb   = blockIdx.y, nb = blockIdx.x;

    const int srow = tid >> 2;
    const int scol = (tid & 3) * 4;
    const float* Ag = A + (size_t)(mb * 128 + srow) * K + scol;
    const float* Bg = B + (size_t)(nb * 128 + srow) * K + scol;
    const size_t g64 = (size_t)64 * K;

    float c[4][4][4];
#pragma unroll
    for (int i = 0; i < 4; i++)
#pragma unroll
        for (int j = 0; j < 4; j++)
#pragma unroll
            for (int q = 0; q < 4; q++) c[i][j][q] = 0.f;

    const int nk = K >> 4;
    float4 ra0, ra1, rb0, rb1;
    ra0 = *(const float4*)(Ag); ra1 = *(const float4*)(Ag + g64);
    rb0 = *(const float4*)(Bg); rb1 = *(const float4*)(Bg + g64);

    int buf = 0;
#define STORE_STAGE(BUF)                                                          \
    {                                                                             \
        uint32_t off = (BUF) * MMSTG;                                             \
        uint32_t h, l;                                                            \
        uint32_t a0 = off + srow * MMROW + scol * 2;                              \
        cvt_hilo(ra0.x, ra0.y, h, l);                                             \
        *(uint32_t*)(sm + a0)        = h; *(uint32_t*)(sm + a0 + 6144)     = l;   \
        cvt_hilo(ra0.z, ra0.w, h, l);                                             \
        *(uint32_t*)(sm + a0 + 4)    = h; *(uint32_t*)(sm + a0 + 6148)     = l;   \
        uint32_t a1 = a0 + 64 * MMROW;                                            \
        cvt_hilo(ra1.x, ra1.y, h, l);                                             \
        *(uint32_t*)(sm + a1)        = h; *(uint32_t*)(sm + a1 + 6144)     = l;   \
        cvt_hilo(ra1.z, ra1.w, h, l);                                             \
        *(uint32_t*)(sm + a1 + 4)    = h; *(uint32_t*)(sm + a1 + 6148)     = l;   \
        uint32_t b0 = off + 12288 + srow * MMROW + scol * 2;                      \
        cvt_hilo(rb0.x, rb0.y, h, l);                                             \
        *(uint32_t*)(sm + b0)        = h; *(uint32_t*)(sm + b0 + 6144)     = l;   \
        cvt_hilo(rb0.z, rb0.w, h, l);                                             \
        *(uint32_t*)(sm + b0 + 4)    = h; *(uint32_t*)(sm + b0 + 6148)     = l;   \
        uint32_t b1 = b0 + 64 * MMROW;                                            \
        cvt_hilo(rb1.x, rb1.y, h, l);                                             \
        *(uint32_t*)(sm + b1)        = h; *(uint32_t*)(sm + b1 + 6144)     = l;   \
        cvt_hilo(rb1.z, rb1.w, h, l);                                             \
        *(uint32_t*)(sm + b1 + 4)    = h; *(uint32_t*)(sm + b1 + 6148)     = l;   \
    }

    STORE_STAGE(0);
    __syncthreads();

    const uint32_t a_lrow = (uint32_t)(wm * 64 + (lane & 15)) * MMROW + ((lane >> 4) * 16);
    const uint32_t b_lrow = (uint32_t)(wn * 32 + (lane & 7)) * MMROW + (((lane >> 3) & 1) * 16);

    for (int kt = 0; kt < nk; kt++) {
        if (kt + 1 < nk) {
            const float* Agn = Ag + (kt + 1) * 16;
            const float* Bgn = Bg + (kt + 1) * 16;
            ra0 = *(const float4*)(Agn); ra1 = *(const float4*)(Agn + g64);
            rb0 = *(const float4*)(Bgn); rb1 = *(const float4*)(Bgn + g64);
        }
        const uint32_t off = buf * MMSTG;
        uint32_t ahi[4][4], alo[4][4];
#pragma unroll
        for (int mf = 0; mf < 4; mf++) {
            uint32_t ad = sbase + off + a_lrow + (uint32_t)mf * 16 * MMROW;
            ldsm_x4(ahi[mf], ad);
            ldsm_x4(alo[mf], ad + 6144);
        }
#pragma unroll
        for (int nf = 0; nf < 4; nf++) {
            uint32_t bd = sbase + off + 12288 + b_lrow + (uint32_t)nf * 8 * MMROW;
            uint32_t bhi[2], blo[2];
            ldsm_x2(bhi, bd);
            ldsm_x2(blo, bd + 6144);
#pragma unroll
            for (int mf = 0; mf < 4; mf++) {
                mma_bf16(c[mf][nf], ahi[mf], bhi);
                mma_bf16(c[mf][nf], ahi[mf], blo);
                mma_bf16(c[mf][nf], alo[mf], bhi);
            }
        }
        if (kt + 1 < nk) {
            STORE_STAGE(buf ^ 1);
            __syncthreads();
            buf ^= 1;
        }
    }
#undef STORE_STAGE

    const int rbase = mb * 128 + wm * 64 + (lane >> 2);
    const int cbase = nb * 128 + wn * 32 + 2 * (lane & 3);
#pragma unroll
    for (int mf = 0; mf < 4; mf++) {
#pragma unroll
        for (int nf = 0; nf < 4; nf++) {
            int col = cbase + nf * 8;
            float b0 = bias[col], b1 = bias[col + 1];
            float v0 = c[mf][nf][0] + b0, v1 = c[mf][nf][1] + b1;
            float v2 = c[mf][nf][2] + b0, v3 = c[mf][nf][3] + b1;
            if (doRelu) {
                v0 = fmaxf(v0, 0.f); v1 = fmaxf(v1, 0.f);
                v2 = fmaxf(v2, 0.f); v3 = fmaxf(v3, 0.f);
            }
            int r0 = rbase + mf * 16;
            *(float2*)(C + (size_t)r0 * N + col)       = make_float2(v0, v1);
            *(float2*)(C + (size_t)(r0 + 8) * N + col) = make_float2(v2, v3);
        }
    }
}

// ---------------- prepack W_hh into B-fragment stream ------------------------------
// One warp per (blk, nf, chunk). n = g*2048 + blk*16 + (nf&1)*8 + (lane>>2),
// k = chunk*16 + 2*(lane&3); regs = {bh(k..), bh(k+8..), bl(k..), bl(k+8..)}.
__global__ __launch_bounds__(256)
void prepack_wf(const float* __restrict__ Whh, uint32_t* __restrict__ WF)
{
    int gw = blockIdx.x * 8 + (threadIdx.x >> 5);   // 0 .. 98303
    int lane = threadIdx.x & 31;
    int chunk = gw & 127;
    int rest  = gw >> 7;
    int nf  = rest % 6;
    int blk = rest / 6;
    int g   = nf >> 1;
    int n   = g * Hh + blk * 16 + (nf & 1) * 8 + (lane >> 2);
    int k   = chunk * 16 + 2 * (lane & 3);
    const float* wr = Whh + (size_t)n * Hh + k;
    uint32_t bh0, bl0, bh1, bl1;
    cvt_hilo(wr[0], wr[1], bh0, bl0);
    cvt_hilo(wr[8], wr[9], bh1, bl1);
    uint32_t* o = WF + ((size_t)gw) * 128 + lane * 4;
    o[0] = bh0; o[1] = bh1; o[2] = bl0; o[3] = bl1;
}

// ---------------- prepack h0 into A-fragment stream --------------------------------
// One warp per (chunk, frag). b = f*16 + (lane>>2) (+8), k = c*16 + 2*(lane&3) (+8).
__global__ __launch_bounds__(256)
void prepack_hf0(const float* __restrict__ h0, uint32_t* __restrict__ HF0)
{
    int gw = blockIdx.x * 8 + (threadIdx.x >> 5);   // 0..255
    int lane = threadIdx.x & 31;
    int c = gw >> 1, f = gw & 1;
    int b = f * 16 + (lane >> 2);
    int k = c * 16 + 2 * (lane & 3);
    const float* p0 = h0 + (size_t)b * Hh + k;
    const float* p1 = h0 + (size_t)(b + 8) * Hh + k;
    uint32_t h0r, l0r, h1r, l1r, h2r, l2r, h3r, l3r;
    cvt_hilo(p0[0], p0[1], h0r, l0r);
    cvt_hilo(p1[0], p1[1], h1r, l1r);
    cvt_hilo(p0[8], p0[9], h2r, l2r);
    cvt_hilo(p1[8], p1[9], h3r, l3r);
    uint32_t* o = HF0 + c * 512 + f * 256 + lane * 4;
    o[0] = h0r; o[1] = h1r; o[2] = h2r; o[3] = h3r;
    o[128] = l0r; o[129] = l1r; o[130] = l2r; o[131] = l3r;
}

__global__ void reset_bar() { g_bar_cnt = 0u; }

// ---------------- persistent mma GRU scan ------------------------------------------
// 128 blocks x 384 threads (12 warps = 6 nfrags x 2 khalves). Block = 16 hcols x 3 gates.
__global__ __launch_bounds__(384, 1)
void gru_scan(const float* __restrict__ gi0,     // row-major (M,3H), r=b*T+t
              const float* __restrict__ h0,      // (B, H)
              const uint32_t* __restrict__ WF,   // packed weights
              const float* __restrict__ bhh,
              float* __restrict__ HSrm,          // (M, H), r=t*32+b
              uint32_t* __restrict__ HFa,        // h frag ping-pong
              uint32_t* __restrict__ HFb)
{
    __shared__ float sred[2][6][32][8];           // 12 KB

    const int tid  = threadIdx.x;
    const int w    = tid >> 5;
    const int lane = tid & 31;
    const int nf   = w % 6;
    const int kh   = w / 6;
    const int blk  = blockIdx.x;
    const int ch0  = kh * 64;

    const uint32_t* wstream = WF + ((size_t)(blk * 6 + nf) * 128 + ch0) * 128 + lane * 4;

    const int ecol = tid >> 4;         // 0..15 (tid<256)
    const int ebp  = tid & 15;
    const int colg = blk * 16 + ecol;
    float br = 0.f, bz = 0.f, bn = 0.f;
    if (tid < 256) { br = bhh[colg]; bz = bhh[Hh + colg]; bn = bhh[2 * Hh + colg]; }

    for (int t = 0; t < Tt; t++) {
        const uint32_t* HFc = ((t & 1) ? HFb : HFa) + lane * 4;
        uint32_t*       HFn = (t & 1) ? HFa : HFb;

        float c0[4] = {0.f, 0.f, 0.f, 0.f};
        float c1[4] = {0.f, 0.f, 0.f, 0.f};

        // depth-4 register ring: [slot][5 x uint4]
        uint4 rb[4][5];
#pragma unroll
        for (int s = 0; s < 4; s++) {
            rb[s][0] = *(const uint4*)(HFc + (ch0 + s) * 512);
            rb[s][1] = *(const uint4*)(HFc + (ch0 + s) * 512 + 128);
            rb[s][2] = *(const uint4*)(HFc + (ch0 + s) * 512 + 256);
            rb[s][3] = *(const uint4*)(HFc + (ch0 + s) * 512 + 384);
            rb[s][4] = *(const uint4*)(wstream + (size_t)s * 128);
        }
        for (int c = 0; c < 64; c += 4) {
#pragma unroll
            for (int u = 0; u < 4; u++) {
                uint4 ah0 = rb[u][0], al0 = rb[u][1];
                uint4 ah1 = rb[u][2], al1 = rb[u][3];
                uint4 bq  = rb[u][4];
                const int cn = c + u + 4;            // prefetch (pads cover overrun)
                rb[u][0] = *(const uint4*)(HFc + (ch0 + cn) * 512);
                rb[u][1] = *(const uint4*)(HFc + (ch0 + cn) * 512 + 128);
                rb[u][2] = *(const uint4*)(HFc + (ch0 + cn) * 512 + 256);
                rb[u][3] = *(const uint4*)(HFc + (ch0 + cn) * 512 + 384);
                rb[u][4] = *(const uint4*)(wstream + (size_t)cn * 128);

                uint32_t bh[2] = {bq.x, bq.y};
                uint32_t bl[2] = {bq.z, bq.w};
                mma_bf16(c0, (const uint32_t*)&ah0, bh);
                mma_bf16(c0, (const uint32_t*)&ah0, bl);
                mma_bf16(c0, (const uint32_t*)&al0, bh);
                mma_bf16(c1, (const uint32_t*)&ah1, bh);
                mma_bf16(c1, (const uint32_t*)&ah1, bl);
                mma_bf16(c1, (const uint32_t*)&al1, bh);
            }
        }

        // store C fragments: rows = batches, cols = n within frag
        {
            float* sp = &sred[kh][nf][0][0];
            int r = lane >> 2, cb = 2 * (lane & 3);
            sp[r * 8 + cb]            = c0[0];
            sp[r * 8 + cb + 1]        = c0[1];
            sp[(r + 8) * 8 + cb]      = c0[2];
            sp[(r + 8) * 8 + cb + 1]  = c0[3];
            sp[(r + 16) * 8 + cb]     = c1[0];
            sp[(r + 16) * 8 + cb + 1] = c1[1];
            sp[(r + 24) * 8 + cb]     = c1[2];
            sp[(r + 24) * 8 + cb + 1] = c1[3];
        }
        __syncthreads();

        if (tid < 256) {
            const int jj = ecol;
            const int nn = jj & 7;
            const int b0 = 2 * ebp, b1 = b0 + 1;
            const int nfr = (jj >> 3);
            float ghr0 = sred[0][0 + nfr][b0][nn] + sred[1][0 + nfr][b0][nn];
            float ghr1 = sred[0][0 + nfr][b1][nn] + sred[1][0 + nfr][b1][nn];
            float ghz0 = sred[0][2 + nfr][b0][nn] + sred[1][2 + nfr][b0][nn];
            float ghz1 = sred[0][2 + nfr][b1][nn] + sred[1][2 + nfr][b1][nn];
            float ghn0 = sred[0][4 + nfr][b0][nn] + sred[1][4 + nfr][b0][nn];
            float ghn1 = sred[0][4 + nfr][b1][nn] + sred[1][4 + nfr][b1][nn];

            const float* gr0 = gi0 + ((size_t)b0 * Tt + t) * H3 + colg;
            const float* gr1 = gi0 + ((size_t)b1 * Tt + t) * H3 + colg;
            const float* hp0 = (t == 0) ? (h0 + (size_t)b0 * Hh)
                                        : (HSrm + ((size_t)(t - 1) * 32 + b0) * Hh);
            const float* hp1 = (t == 0) ? (h0 + (size_t)b1 * Hh)
                                        : (HSrm + ((size_t)(t - 1) * 32 + b1) * Hh);
            float hv0 = hp0[colg], hv1 = hp1[colg];

            float rx = sigm(gr0[0] + ghr0 + br);
            float ry = sigm(gr1[0] + ghr1 + br);
            float zx = sigm(gr0[Hh] + ghz0 + bz);
            float zy = sigm(gr1[Hh] + ghz1 + bz);
            float nx = tanhf(gr0[2 * Hh] + rx * (ghn0 + bn));
            float ny = tanhf(gr1[2 * Hh] + ry * (ghn1 + bn));
            float hn0 = (1.f - zx) * nx + zx * hv0;
            float hn1 = (1.f - zy) * ny + zy * hv1;

            HSrm[((size_t)t * 32 + b0) * Hh + colg] = hn0;
            HSrm[((size_t)t * 32 + b1) * Hh + colg] = hn1;

            // write h fragments for next step (bf16 hi/lo, scattered 2B)
            const int cch = colg >> 4, kk = colg & 15;
            const int lidx = ((0) | ((kk >> 1) & 3));  // partial; complete per batch
#pragma unroll
            for (int bi = 0; bi < 2; bi++) {
                int b = b0 + bi;
                float hv = bi ? hn1 : hn0;
                int f = b >> 4, r = b & 15;
                int ln = ((r & 7) << 2) | (lidx);
                int rg = ((r >> 3) & 1) | (((kk >> 3) & 1) << 1);
                int idx_hi = cch * 512 + f * 256 + ln * 4 + rg;
                __nv_bfloat16 hh = __float2bfloat16(hv);
                __nv_bfloat16 hl = __float2bfloat16(hv - __bfloat162float(hh));
                ((__nv_bfloat16*)HFn)[2 * idx_hi + (kk & 1)]         = hh;
                ((__nv_bfloat16*)HFn)[2 * (idx_hi + 128) + (kk & 1)] = hl;
            }
        }

        // -------- grid sync --------
        __syncthreads();
        if (tid == 0) {
            __threadfence();
            atomicAdd(&g_bar_cnt, 1u);
            const unsigned target = (unsigned)(t + 1) * GRID_SCAN;
            unsigned v;
            do {
                asm volatile("ld.global.acquire.gpu.b32 %0, [%1];" : "=r"(v) : "l"(&g_bar_cnt));
                if (v >= target) break;
                __nanosleep(64);
            } while (true);
        }
        __syncthreads();
    }
}

// ---------------- head --------------------------------------------------------------
__global__ __launch_bounds__(256)
void head_kernel(const float* __restrict__ S, const float* __restrict__ Wp,
                 const float* __restrict__ bp, const int* __restrict__ label,
                 float* __restrict__ out)
{
    int w    = blockIdx.x * 8 + (threadIdx.x >> 5);
    int lane = threadIdx.x & 31;
    int bt = w / 3, j = w % 3;
    int t = bt >> 5, b = bt & 31;        // S row = t*32 + b
    int lab = label[b];
    const float* sp = S  + (size_t)bt * Pp;
    const float* wp = Wp + (size_t)(j * 8 + lab) * Pp;
    float sum = 0.f;
    for (int d = lane; d < Pp; d += 32)
        sum = fmaf(sp[d], wp[d], sum);
#pragma unroll
    for (int o = 16; o > 0; o >>= 1) sum += __shfl_xor_sync(0xffffffffu, sum, o);
    if (lane == 0)
        out[(size_t)b * Tt * 3 + t * 3 + j] = sum + bp[j * 8 + lab];
}

__global__ void copy_hlast(const float* __restrict__ HSrm, float* __restrict__ dst)
{
    int i = blockIdx.x * 256 + threadIdx.x;   // i = b*Hh + c
    if (i < Bb * Hh) {
        int b = i >> 11, c = i & (Hh - 1);
        dst[i] = HSrm[((size_t)(Tt - 1) * 32 + b) * Hh + c];
    }
}

// ---------------- launch ------------------------------------------------------------
extern "C" void kernel_launch(void* const* d_in, const int* in_sizes, int n_in,
                              void* d_out, int out_size)
{
    (void)in_sizes; (void)n_in; (void)out_size;
    const float* x     = (const float*)d_in[0];
    const int*   label = (const int*)  d_in[1];
    const float* h0    = (const float*)d_in[2];
    const float* W1  = (const float*)d_in[3];  const float* b1  = (const float*)d_in[4];
    const float* W2  = (const float*)d_in[5];  const float* b2  = (const float*)d_in[6];
    const float* Wih = (const float*)d_in[7];  const float* bih = (const float*)d_in[8];
    const float* Whh = (const float*)d_in[9];  const float* bhh = (const float*)d_in[10];
    const float* W3  = (const float*)d_in[11]; const float* b3  = (const float*)d_in[12];
    const float* Wp  = (const float*)d_in[13]; const float* bp  = (const float*)d_in[14];
    float* out = (float*)d_out;

    float *A1, *A2, *GI, *HS, *S;
    uint32_t *WF, *HF;
    cudaGetSymbolAddress((void**)&A1, g_A1);
    cudaGetSymbolAddress((void**)&A2, g_A2);
    cudaGetSymbolAddress((void**)&GI, g_GI);
    cudaGetSymbolAddress((void**)&HS, g_HS);
    cudaGetSymbolAddress((void**)&S,  g_S);
    cudaGetSymbolAddress((void**)&WF, g_WF);
    cudaGetSymbolAddress((void**)&HF, g_HF);
    uint32_t* HFa = HF;
    uint32_t* HFb = HF + (128 * 512 + 4 * 512);

    prepack_wf<<<98304 / 8, 256>>>(Whh, WF);
    prepack_hf0<<<256 / 8, 256>>>(h0, HFa);
    reset_bar<<<1, 1>>>();

    // all four big GEMMs on tensor cores (split-bf16, 3 passes)
    mma_gemm<<<dim3(1024 / 128, MT / 128), 256, 2 * MMSTG>>>(x,  W1, b1, A1, MT, 1024, Dd, 1);
    mma_gemm<<<dim3(Hh   / 128, MT / 128), 256, 2 * MMSTG>>>(A1, W2, b2, A2, MT, Hh, 1024, 1);
    mma_gemm<<<dim3(H3   / 128, MT / 128), 256, 2 * MMSTG>>>(A2, Wih, bih, GI, MT, H3, Hh, 0);

    // persistent tensor-core GRU scan
    gru_scan<<<GRID_SCAN, 384>>>(GI, h0, WF, bhh, HS, HFa, HFb);

    // W3 on HS row-major (rows r = t*32+b)
    mma_gemm<<<dim3(Pp / 128, MT / 128), 256, 2 * MMSTG>>>(HS, W3, b3, S, MT, Pp, Hh, 1);

    head_kernel<<<6144, 256>>>(S, Wp, bp, label, out);
    copy_hlast<<<(Bb * Hh + 255) / 256, 256>>>(HS, out + Bb * Tt * 3);
}